// round 1
// baseline (speedup 1.0000x reference)
#include <cuda_runtime.h>
#include <cstdint>

#define NB 16
#define KG 50
#define HH 64
#define WW 64
#define NA 9
#define NN (HH*WW*NA)      // 36864
#define HALF_NN (NN/2)     // 18432

// PRNG mode: 1 = threefry_partitionable (modern JAX default), 0 = original halved-counter path
#define PRNG_MODE 1

// base anchors (ratios 0.5/1/2 x scales 8/16/32), exact fp32 values
__constant__ float c_base[NA][4] = {
  { -84.f,  -40.f,  99.f,  55.f},   // 184x96
  {-176.f,  -88.f, 191.f, 103.f},   // 368x192
  {-360.f, -184.f, 375.f, 199.f},   // 736x384
  { -56.f,  -56.f,  71.f,  71.f},   // 128x128
  {-120.f, -120.f, 135.f, 135.f},   // 256x256
  {-248.f, -248.f, 263.f, 263.f},   // 512x512
  { -36.f,  -80.f,  51.f,  95.f},   // 88x176
  { -80.f, -168.f,  95.f, 183.f},   // 176x352
  {-168.f, -344.f, 183.f, 359.f}    // 352x704
};

__device__ float          g_gtmax[NB][KG];
__device__ unsigned char  g_lab[NB][NN];     // 0:-1  1:bg  2:fg  3:outside
__device__ unsigned short g_arg[NB][NN];
__device__ unsigned int   g_r[NB][NN];       // 23-bit random mantissa for candidates
__device__ unsigned int   g_hist[NB][2][2048];
__device__ int            g_cnt[NB][2];
__device__ uint2          g_thr[NB][2];      // (r*, idx_thr): keep iff r>r* || (r==r* && i<=idx_thr)
__device__ float          g_uw[NB];

struct Keys { unsigned int kf[NB][2]; unsigned int kb[NB][2]; };

__host__ __device__ __forceinline__ unsigned int rotl32(unsigned int x, int r) {
  return (x << r) | (x >> (32 - r));
}

__host__ __device__ __forceinline__ void tf2x32(unsigned int k0, unsigned int k1,
                                                unsigned int x0, unsigned int x1,
                                                unsigned int &o0, unsigned int &o1) {
  unsigned int ks2 = k0 ^ k1 ^ 0x1BD11BDAu;
  x0 += k0; x1 += k1;
  const int ra[4] = {13, 15, 26, 6};
  const int rb[4] = {17, 29, 16, 24};
  #pragma unroll
  for (int j = 0; j < 4; j++) { x0 += x1; x1 = rotl32(x1, ra[j]); x1 ^= x0; }
  x0 += k1;  x1 += ks2 + 1u;
  #pragma unroll
  for (int j = 0; j < 4; j++) { x0 += x1; x1 = rotl32(x1, rb[j]); x1 ^= x0; }
  x0 += ks2; x1 += k0 + 2u;
  #pragma unroll
  for (int j = 0; j < 4; j++) { x0 += x1; x1 = rotl32(x1, ra[j]); x1 ^= x0; }
  x0 += k0;  x1 += k1 + 3u;
  #pragma unroll
  for (int j = 0; j < 4; j++) { x0 += x1; x1 = rotl32(x1, rb[j]); x1 ^= x0; }
  x0 += k1;  x1 += ks2 + 4u;
  #pragma unroll
  for (int j = 0; j < 4; j++) { x0 += x1; x1 = rotl32(x1, ra[j]); x1 ^= x0; }
  x0 += ks2; x1 += k0 + 5u;
  o0 = x0; o1 = x1;
}

// IEEE, no-FMA IoU so both passes (and XLA) produce identical bits
__device__ __forceinline__ float iou_fn(float ax1, float ay1, float ax2, float ay2, float aarea,
                                        float gx1, float gy1, float gx2, float gy2, float garea) {
  float ix = __fadd_rn(__fsub_rn(fminf(ax2, gx2), fmaxf(ax1, gx1)), 1.0f);
  ix = fmaxf(0.0f, ix);
  float iy = __fadd_rn(__fsub_rn(fminf(ay2, gy2), fmaxf(ay1, gy1)), 1.0f);
  iy = fmaxf(0.0f, iy);
  float inter = __fmul_rn(ix, iy);
  float denom = __fsub_rn(__fadd_rn(aarea, garea), inter);
  return __fdiv_rn(inter, denom);
}

__device__ __forceinline__ void load_gts(const float* __restrict__ gt_boxes, int b, int t,
                                         float (*s_g)[4], float* s_ga) {
  if (t < KG) {
    const float* g = gt_boxes + (b * KG + t) * 5;
    float g0 = g[0], g1 = g[1], g2 = g[2], g3 = g[3];
    s_g[t][0] = g0; s_g[t][1] = g1; s_g[t][2] = g2; s_g[t][3] = g3;
    s_ga[t] = __fmul_rn(__fadd_rn(__fsub_rn(g2, g0), 1.0f),
                        __fadd_rn(__fsub_rn(g3, g1), 1.0f));
  }
}

__global__ void k_init() {
  int idx = blockIdx.x * blockDim.x + threadIdx.x;
  if (idx < NB * 2 * 2048) ((unsigned int*)g_hist)[idx] = 0u;
  if (idx < NB * KG)       ((float*)g_gtmax)[idx] = 0.0f;
  if (idx < NB * 2)        ((int*)g_cnt)[idx] = 0;
}

__global__ void k_gtmax(const float* __restrict__ gt_boxes, const float* __restrict__ im_info) {
  __shared__ float s_g[KG][4];
  __shared__ float s_ga[KG];
  int b = blockIdx.y;
  int t = threadIdx.x;
  load_gts(gt_boxes, b, t, s_g, s_ga);
  __syncthreads();
  int i = blockIdx.x * blockDim.x + t;
  if (i >= NN) return;
  float img_h = im_info[0], img_w = im_info[1];
  int a = i % NA; int hw = i / NA; int w = hw % WW; int h = hw / WW;
  float sx = (float)(w * 16), sy = (float)(h * 16);
  float ax1 = c_base[a][0] + sx, ay1 = c_base[a][1] + sy;
  float ax2 = c_base[a][2] + sx, ay2 = c_base[a][3] + sy;
  bool inside = (ax1 >= 0.f) && (ay1 >= 0.f) && (ax2 < img_w) && (ay2 < img_h);
  if (!inside) return;
  float aw = __fadd_rn(__fsub_rn(ax2, ax1), 1.0f);
  float ah = __fadd_rn(__fsub_rn(ay2, ay1), 1.0f);
  float aarea = __fmul_rn(aw, ah);
  #pragma unroll 5
  for (int k = 0; k < KG; k++) {
    float ov = iou_fn(ax1, ay1, ax2, ay2, aarea, s_g[k][0], s_g[k][1], s_g[k][2], s_g[k][3], s_ga[k]);
    if (ov > 0.f) atomicMax((int*)&g_gtmax[b][k], __float_as_int(ov));
  }
}

__global__ void k_label(const float* __restrict__ gt_boxes, const float* __restrict__ im_info,
                        Keys keys) {
  __shared__ float s_g[KG][4];
  __shared__ float s_ga[KG];
  __shared__ float s_gm[KG];
  int b = blockIdx.y;
  int t = threadIdx.x;
  load_gts(gt_boxes, b, t, s_g, s_ga);
  if (t < KG) {
    float gm = g_gtmax[b][t];
    s_gm[t] = (gm == 0.f) ? 1e-5f : gm;
  }
  __syncthreads();
  int i = blockIdx.x * blockDim.x + t;
  if (i >= NN) return;
  float img_h = im_info[0], img_w = im_info[1];
  int a = i % NA; int hw = i / NA; int w = hw % WW; int h = hw / WW;
  float sx = (float)(w * 16), sy = (float)(h * 16);
  float ax1 = c_base[a][0] + sx, ay1 = c_base[a][1] + sy;
  float ax2 = c_base[a][2] + sx, ay2 = c_base[a][3] + sy;
  bool inside = (ax1 >= 0.f) && (ay1 >= 0.f) && (ax2 < img_w) && (ay2 < img_h);
  if (!inside) { g_lab[b][i] = 3; return; }
  float aw = __fadd_rn(__fsub_rn(ax2, ax1), 1.0f);
  float ah = __fadd_rn(__fsub_rn(ay2, ay1), 1.0f);
  float aarea = __fmul_rn(aw, ah);
  float maxov = -1.0f; int arg = 0; bool best = false;
  #pragma unroll 5
  for (int k = 0; k < KG; k++) {
    float ov = iou_fn(ax1, ay1, ax2, ay2, aarea, s_g[k][0], s_g[k][1], s_g[k][2], s_g[k][3], s_ga[k]);
    if (ov > maxov) { maxov = ov; arg = k; }
    if (ov == s_gm[k]) best = true;
  }
  unsigned char code;
  if (best || (maxov >= 0.7f)) code = 2;
  else if (maxov < 0.3f)       code = 1;
  else                         code = 0;
  g_lab[b][i] = code;
  g_arg[b][i] = (unsigned short)arg;
  if (code >= 1) {
    unsigned int k0 = (code == 2) ? keys.kf[b][0] : keys.kb[b][0];
    unsigned int k1 = (code == 2) ? keys.kf[b][1] : keys.kb[b][1];
    unsigned int o0, o1, bits;
#if PRNG_MODE
    tf2x32(k0, k1, 0u, (unsigned int)i, o0, o1);
    bits = o0 ^ o1;
#else
    if (i < HALF_NN) { tf2x32(k0, k1, (unsigned int)i, (unsigned int)(i + HALF_NN), o0, o1); bits = o0; }
    else             { tf2x32(k0, k1, (unsigned int)(i - HALF_NN), (unsigned int)i, o0, o1); bits = o1; }
#endif
    unsigned int r = bits >> 9;   // 23-bit mantissa; uniform is strictly monotonic in r
    g_r[b][i] = r;
    int type = (code == 2) ? 0 : 1;
    atomicAdd(&g_cnt[b][type], 1);
    atomicAdd(&g_hist[b][type][r >> 12], 1u);
  }
}

// One block per (batch, type): find exact K-th largest key (r desc, idx asc)
__global__ void k_select() {
  __shared__ unsigned int h2[4096];
  __shared__ unsigned int lst[2048];
  __shared__ int s_t, s_K1, s_K2, s_done, s_lc;
  __shared__ unsigned int s_rstar;

  int b = blockIdx.x >> 1;
  int type = blockIdx.x & 1;
  int t = threadIdx.x;

  int cnt = g_cnt[b][type];
  int kept_fg = min(g_cnt[b][0], 128);
  int K = (type == 0) ? 128 : (256 - kept_fg);
  if (type == 1 && t == 0) {
    int kept_bg = min(cnt, K);
    g_uw[b] = __fdiv_rn(1.0f, (float)(kept_fg + kept_bg));
  }
  if (cnt <= K) {
    if (t == 0) g_thr[b][type] = make_uint2(0u, 0xFFFFFFFFu);  // keep all
    return;
  }
  if (t == 0) {
    int cum = 0, tb = 0, K1 = K;
    for (int j = 2047; j >= 0; j--) {
      int hj = (int)g_hist[b][type][j];
      if (cum + hj >= K) { tb = j; K1 = K - cum; break; }
      cum += hj;
    }
    s_t = tb; s_K1 = K1;
  }
  for (int j = t; j < 4096; j += blockDim.x) h2[j] = 0u;
  __syncthreads();
  int tb = s_t;
  unsigned char want = (type == 0) ? 2 : 1;
  for (int i = t; i < NN; i += blockDim.x) {
    if (g_lab[b][i] == want) {
      unsigned int r = g_r[b][i];
      if ((int)(r >> 12) == tb) atomicAdd(&h2[r & 0xFFFu], 1u);
    }
  }
  __syncthreads();
  if (t == 0) {
    int cum = 0, K1 = s_K1, rl = 0, K2 = K1, ceq = 1;
    for (int j = 4095; j >= 0; j--) {
      int hj = (int)h2[j];
      if (cum + hj >= K1) { rl = j; K2 = K1 - cum; ceq = hj; break; }
      cum += hj;
    }
    s_rstar = ((unsigned int)tb << 12) | (unsigned int)rl;
    s_K2 = K2;
    s_done = (K2 == ceq);
    if (s_done) g_thr[b][type] = make_uint2(s_rstar, 0xFFFFFFFFu);
    s_lc = 0;
  }
  __syncthreads();
  if (s_done) return;
  unsigned int rstar = s_rstar;
  for (int i = t; i < NN; i += blockDim.x) {
    if (g_lab[b][i] == want && g_r[b][i] == rstar) {
      int p = atomicAdd(&s_lc, 1);
      if (p < 2048) lst[p] = (unsigned int)i;
    }
  }
  __syncthreads();
  if (t == 0) {
    int c = min(s_lc, 2048);
    for (int x = 1; x < c; x++) {         // tiny insertion sort (ties are rare)
      unsigned int v = lst[x]; int y = x - 1;
      while (y >= 0 && lst[y] > v) { lst[y + 1] = lst[y]; y--; }
      lst[y + 1] = v;
    }
    int k2 = s_K2; if (k2 > c) k2 = c;
    g_thr[b][type] = make_uint2(rstar, lst[k2 - 1]);
  }
}

__global__ void k_out(const float* __restrict__ gt_boxes, float* __restrict__ out) {
  const int TBASE = NB * NN;                 // 589824
  const int IBASE = TBASE + NB * NN * 4;     // 2949120
  const int OBASE = IBASE + NB * NN * 4;     // 5308416
  int bid = blockIdx.x;
  int hblk = bid % (HH / 4);
  int tmp = bid / (HH / 4);
  int a = tmp % NA;
  int b = tmp / NA;
  int w = threadIdx.x & 63;
  int h = hblk * 4 + (threadIdx.x >> 6);
  int i = (h * WW + w) * NA + a;

  int base_l = b * NN + (a * HH + h) * WW + w;
  int off = b * (NN * 4) + h * WW + w;

  unsigned char code = g_lab[b][i];
  if (code == 3) {  // outside: everything zero
    out[base_l] = 0.f;
    #pragma unroll
    for (int c = 0; c < 4; c++) {
      int o = off + (a * 4 + c) * (HH * WW);
      out[TBASE + o] = 0.f; out[IBASE + o] = 0.f; out[OBASE + o] = 0.f;
    }
    return;
  }
  float lblv; bool is_pos = false, counted = false;
  if (code == 0) lblv = -1.f;
  else {
    int type = (code == 2) ? 0 : 1;
    uint2 thr = g_thr[b][type];
    unsigned int r = g_r[b][i];
    bool keep = (r > thr.x) || ((r == thr.x) && ((unsigned int)i <= thr.y));
    if (code == 2) { lblv = keep ? 1.f : -1.f; is_pos = keep; counted = keep; }
    else           { lblv = keep ? 0.f : -1.f; counted = keep; }
  }
  out[base_l] = lblv;

  int arg = g_arg[b][i];
  const float* g = gt_boxes + (b * KG + arg) * 5;
  float g0 = g[0], g1 = g[1], g2 = g[2], g3 = g[3];
  float sx = (float)(w * 16), sy = (float)(h * 16);
  float ax1 = c_base[a][0] + sx, ay1 = c_base[a][1] + sy;
  float ax2 = c_base[a][2] + sx, ay2 = c_base[a][3] + sy;
  float aw = ax2 - ax1 + 1.f, ah = ay2 - ay1 + 1.f;
  float acx = ax1 + 0.5f * (aw - 1.f), acy = ay1 + 0.5f * (ah - 1.f);
  float gw = g2 - g0 + 1.f, gh = g3 - g1 + 1.f;
  float gcx = g0 + 0.5f * (gw - 1.f), gcy = g1 + 0.5f * (gh - 1.f);
  float tx = (gcx - acx) / aw, ty = (gcy - acy) / ah;
  float tw = logf(gw / aw), th = logf(gh / ah);

  float inw = is_pos ? 1.f : 0.f;
  float ow  = counted ? g_uw[b] : 0.f;
  float tgt[4] = {tx, ty, tw, th};
  #pragma unroll
  for (int c = 0; c < 4; c++) {
    int o = off + (a * 4 + c) * (HH * WW);
    out[TBASE + o] = tgt[c];
    out[IBASE + o] = inw;
    out[OBASE + o] = ow;
  }
}

extern "C" void kernel_launch(void* const* d_in, const int* in_sizes, int n_in,
                              void* d_out, int out_size) {
  const float* gt = (const float*)d_in[1];
  const float* iminfo = (const float*)d_in[2];
  float* out = (float*)d_out;

  Keys keys;
#if PRNG_MODE
  // partitionable: key_b = tf(key,(0,b)); kf = tf(key_b,(0,0)); kb = tf(key_b,(0,1))
  for (int b = 0; b < NB; b++) {
    unsigned int a0, a1;
    tf2x32(0u, 42u, 0u, (unsigned int)b, a0, a1);
    tf2x32(a0, a1, 0u, 0u, keys.kf[b][0], keys.kf[b][1]);
    tf2x32(a0, a1, 0u, 1u, keys.kb[b][0], keys.kb[b][1]);
  }
#else
  // original: counts iota(2n) halved into lanes
  unsigned int o0[NB], o1[NB], outv[2 * NB];
  for (int i = 0; i < NB; i++) tf2x32(0u, 42u, (unsigned int)i, (unsigned int)(i + NB), o0[i], o1[i]);
  for (int j = 0; j < NB; j++) { outv[j] = o0[j]; outv[NB + j] = o1[j]; }
  for (int b = 0; b < NB; b++) {
    unsigned int kb0 = outv[2 * b], kb1 = outv[2 * b + 1];
    unsigned int f0, q0, f1, q1;
    tf2x32(kb0, kb1, 0u, 2u, f0, q0);
    tf2x32(kb0, kb1, 1u, 3u, f1, q1);
    keys.kf[b][0] = f0; keys.kf[b][1] = f1;
    keys.kb[b][0] = q0; keys.kb[b][1] = q1;
  }
#endif

  k_init<<<256, 256>>>();
  dim3 g1((NN + 255) / 256, NB);
  k_gtmax<<<g1, 256>>>(gt, iminfo);
  k_label<<<g1, 256>>>(gt, iminfo, keys);
  k_select<<<NB * 2, 256>>>();
  k_out<<<NB * NA * (HH / 4), 256>>>(gt, out);
}

// round 2
// speedup vs baseline: 2.7647x; 2.7647x over previous
#include <cuda_runtime.h>
#include <cstdint>

#define NB 16
#define KG 50
#define HH 64
#define WW 64
#define NA 9
#define NN (HH*WW*NA)      // 36864
#define HW (HH*WW)         // 4096

// PRNG mode: 1 = threefry_partitionable (modern JAX default)
#define PRNG_MODE 1

#define SEL_CAP 2048

// base anchors (ratios 0.5/1/2 x scales 8/16/32), exact fp32 values
__constant__ float c_base[NA][4] = {
  { -84.f,  -40.f,  99.f,  55.f},
  {-176.f,  -88.f, 191.f, 103.f},
  {-360.f, -184.f, 375.f, 199.f},
  { -56.f,  -56.f,  71.f,  71.f},
  {-120.f, -120.f, 135.f, 135.f},
  {-248.f, -248.f, 263.f, 263.f},
  { -36.f,  -80.f,  51.f,  95.f},
  { -80.f, -168.f,  95.f, 183.f},
  {-168.f, -344.f, 183.f, 359.f}
};

__device__ float          g_gtmax[NB][KG];
__device__ unsigned char  g_lab[NB][NN];     // 0:-1  1:bg  2:fg  3:outside
__device__ unsigned short g_arg[NB][NN];
__device__ unsigned int   g_r[NB][NN];       // 23-bit random mantissa for candidates
__device__ unsigned int   g_hist[NB][2][2048];
__device__ uint2          g_thr[NB][2];      // keep iff r>thr.x || (r==thr.x && i<=thr.y)
__device__ float          g_uw[NB];

struct Keys { unsigned int kf[NB][2]; unsigned int kb[NB][2]; };

__host__ __device__ __forceinline__ unsigned int rotl32(unsigned int x, int r) {
  return (x << r) | (x >> (32 - r));
}

__host__ __device__ __forceinline__ void tf2x32(unsigned int k0, unsigned int k1,
                                                unsigned int x0, unsigned int x1,
                                                unsigned int &o0, unsigned int &o1) {
  unsigned int ks2 = k0 ^ k1 ^ 0x1BD11BDAu;
  x0 += k0; x1 += k1;
  const int ra[4] = {13, 15, 26, 6};
  const int rb[4] = {17, 29, 16, 24};
  #pragma unroll
  for (int j = 0; j < 4; j++) { x0 += x1; x1 = rotl32(x1, ra[j]); x1 ^= x0; }
  x0 += k1;  x1 += ks2 + 1u;
  #pragma unroll
  for (int j = 0; j < 4; j++) { x0 += x1; x1 = rotl32(x1, rb[j]); x1 ^= x0; }
  x0 += ks2; x1 += k0 + 2u;
  #pragma unroll
  for (int j = 0; j < 4; j++) { x0 += x1; x1 = rotl32(x1, ra[j]); x1 ^= x0; }
  x0 += k0;  x1 += k1 + 3u;
  #pragma unroll
  for (int j = 0; j < 4; j++) { x0 += x1; x1 = rotl32(x1, rb[j]); x1 ^= x0; }
  x0 += k1;  x1 += ks2 + 4u;
  #pragma unroll
  for (int j = 0; j < 4; j++) { x0 += x1; x1 = rotl32(x1, ra[j]); x1 ^= x0; }
  x0 += ks2; x1 += k0 + 5u;
  o0 = x0; o1 = x1;
}

__device__ __forceinline__ void load_gts(const float* __restrict__ gt_boxes, int b, int t,
                                         float (*s_g)[4], float* s_ga) {
  if (t < KG) {
    const float* g = gt_boxes + (b * KG + t) * 5;
    float g0 = g[0], g1 = g[1], g2 = g[2], g3 = g[3];
    s_g[t][0] = g0; s_g[t][1] = g1; s_g[t][2] = g2; s_g[t][3] = g3;
    s_ga[t] = __fmul_rn(__fadd_rn(__fsub_rn(g2, g0), 1.0f),
                        __fadd_rn(__fsub_rn(g3, g1), 1.0f));
  }
}

__global__ void k_init() {
  int idx = blockIdx.x * blockDim.x + threadIdx.x;
  if (idx < NB * 2 * 2048) ((unsigned int*)g_hist)[idx] = 0u;
  if (idx < NB * KG)       ((float*)g_gtmax)[idx] = 0.0f;
}

// grid (HW/256, NA, NB): warp = one anchor shape, contiguous hw
__global__ void k_gtmax(const float* __restrict__ gt_boxes, const float* __restrict__ im_info) {
  __shared__ float s_g[KG][4];
  __shared__ float s_ga[KG];
  int b = blockIdx.z;
  int a = blockIdx.y;
  int t = threadIdx.x;
  load_gts(gt_boxes, b, t, s_g, s_ga);
  __syncthreads();
  int hw = blockIdx.x * blockDim.x + t;
  float img_h = im_info[0], img_w = im_info[1];
  int w = hw & 63; int h = hw >> 6;
  float sx = (float)(w * 16), sy = (float)(h * 16);
  float ax1 = c_base[a][0] + sx, ay1 = c_base[a][1] + sy;
  float ax2 = c_base[a][2] + sx, ay2 = c_base[a][3] + sy;
  bool inside = (ax1 >= 0.f) && (ay1 >= 0.f) && (ax2 < img_w) && (ay2 < img_h);
  if (!inside) return;
  float aw = __fadd_rn(__fsub_rn(ax2, ax1), 1.0f);
  float ah = __fadd_rn(__fsub_rn(ay2, ay1), 1.0f);
  float aarea = __fmul_rn(aw, ah);
  unsigned mask = __activemask();
  int lane = t & 31;
  int leader = __ffs(mask) - 1;
  #pragma unroll 5
  for (int k = 0; k < KG; k++) {
    float ix = __fadd_rn(__fsub_rn(fminf(ax2, s_g[k][2]), fmaxf(ax1, s_g[k][0])), 1.0f);
    float iy = __fadd_rn(__fsub_rn(fminf(ay2, s_g[k][3]), fmaxf(ay1, s_g[k][1])), 1.0f);
    int ovb = 0;
    if (ix > 0.f && iy > 0.f) {
      float inter = __fmul_rn(ix, iy);
      float denom = __fsub_rn(__fadd_rn(aarea, s_ga[k]), inter);
      ovb = __float_as_int(__fdiv_rn(inter, denom));
    }
    int mv = __reduce_max_sync(mask, ovb);
    if (lane == leader && mv > 0) atomicMax((int*)&g_gtmax[b][k], mv);
  }
}

__global__ void k_label(const float* __restrict__ gt_boxes, const float* __restrict__ im_info,
                        Keys keys) {
  __shared__ float s_g[KG][4];
  __shared__ float s_ga[KG];
  __shared__ float s_gm[KG];
  int b = blockIdx.z;
  int a = blockIdx.y;
  int t = threadIdx.x;
  load_gts(gt_boxes, b, t, s_g, s_ga);
  if (t < KG) {
    float gm = g_gtmax[b][t];
    s_gm[t] = (gm == 0.f) ? 1e-5f : gm;
  }
  __syncthreads();
  int hw = blockIdx.x * blockDim.x + t;
  int i = hw * NA + a;
  float img_h = im_info[0], img_w = im_info[1];
  int w = hw & 63; int h = hw >> 6;
  float sx = (float)(w * 16), sy = (float)(h * 16);
  float ax1 = c_base[a][0] + sx, ay1 = c_base[a][1] + sy;
  float ax2 = c_base[a][2] + sx, ay2 = c_base[a][3] + sy;
  bool inside = (ax1 >= 0.f) && (ay1 >= 0.f) && (ax2 < img_w) && (ay2 < img_h);
  if (!inside) { g_lab[b][i] = 3; return; }
  float aw = __fadd_rn(__fsub_rn(ax2, ax1), 1.0f);
  float ah = __fadd_rn(__fsub_rn(ay2, ay1), 1.0f);
  float aarea = __fmul_rn(aw, ah);
  float maxov = 0.0f; int arg = 0; bool best = false;
  #pragma unroll 5
  for (int k = 0; k < KG; k++) {
    float ix = __fadd_rn(__fsub_rn(fminf(ax2, s_g[k][2]), fmaxf(ax1, s_g[k][0])), 1.0f);
    float iy = __fadd_rn(__fsub_rn(fminf(ay2, s_g[k][3]), fmaxf(ay1, s_g[k][1])), 1.0f);
    if (ix > 0.f && iy > 0.f) {
      float inter = __fmul_rn(ix, iy);
      float denom = __fsub_rn(__fadd_rn(aarea, s_ga[k]), inter);
      float ov = __fdiv_rn(inter, denom);
      if (ov > maxov) { maxov = ov; arg = k; }
      if (ov == s_gm[k]) best = true;
    }
  }
  unsigned char code;
  if (best || (maxov >= 0.7f)) code = 2;
  else if (maxov < 0.3f)       code = 1;
  else                         code = 0;
  g_lab[b][i] = code;
  g_arg[b][i] = (unsigned short)arg;
  if (code >= 1) {
    unsigned int k0 = (code == 2) ? keys.kf[b][0] : keys.kb[b][0];
    unsigned int k1 = (code == 2) ? keys.kf[b][1] : keys.kb[b][1];
    unsigned int o0, o1, bits;
    tf2x32(k0, k1, 0u, (unsigned int)i, o0, o1);
    bits = o0 ^ o1;
    unsigned int r = bits >> 9;   // 23-bit mantissa; uniform is strictly monotonic in r
    g_r[b][i] = r;
    int type = (code == 2) ? 0 : 1;
    atomicAdd(&g_hist[b][type][r >> 12], 1u);
  }
}

// One block per batch; both types. Parallel suffix scan + single collect pass.
__global__ void k_select() {
  __shared__ unsigned int sh[2048];
  __shared__ unsigned int ss[257];
  __shared__ unsigned long long lst[SEL_CAP];
  __shared__ int s_tb, s_K1, s_lc;
  __shared__ int s_kept[2];

  int b = blockIdx.x;
  int t = threadIdx.x;

  for (int type = 0; type < 2; type++) {
    int K = (type == 0) ? 128 : (256 - s_kept[0]);
    for (int j = t; j < 2048; j += 256) sh[j] = g_hist[b][type][j];
    if (t == 0) { ss[256] = 0u; s_lc = 0; }
    __syncthreads();
    unsigned int cs = 0;
    #pragma unroll
    for (int k = 0; k < 8; k++) cs += sh[t * 8 + k];
    ss[t] = cs;
    __syncthreads();
    // Hillis-Steele inclusive suffix sum over 256 chunk sums
    #pragma unroll
    for (int off = 1; off < 256; off <<= 1) {
      unsigned int v = (t + off < 256) ? ss[t + off] : 0u;
      __syncthreads();
      ss[t] += v;
      __syncthreads();
    }
    int cnt = (int)ss[0];
    if (t == 0) s_kept[type] = min(cnt, K);
    if (cnt <= K) {
      if (t == 0) g_thr[b][type] = make_uint2(0u, 0xFFFFFFFFu);  // keep all
      __syncthreads();
      continue;
    }
    // per-thread search for the threshold bin (unique finder)
    {
      int run = (int)ss[t + 1];   // count in bins strictly above this chunk
      #pragma unroll
      for (int k = 7; k >= 0; k--) {
        int j = t * 8 + k;
        int hj = (int)sh[j];
        if (run < K && run + hj >= K) { s_tb = j; s_K1 = K - run; }
        run += hj;
      }
    }
    __syncthreads();
    int tb = s_tb;
    unsigned char want = (type == 0) ? 2 : 1;
    for (int i = t; i < NN; i += 256) {
      if (g_lab[b][i] == want) {
        unsigned int r = g_r[b][i];
        if ((int)(r >> 12) == tb) {
          int p = atomicAdd(&s_lc, 1);
          if (p < SEL_CAP)
            lst[p] = ((unsigned long long)r << 32) | (unsigned long long)(0xFFFFFFFFu - (unsigned int)i);
        }
      }
    }
    __syncthreads();
    if (t == 0) {
      int n = min(s_lc, SEL_CAP);
      for (int x = 1; x < n; x++) {     // descending insertion sort (n is small)
        unsigned long long v = lst[x]; int y = x - 1;
        while (y >= 0 && lst[y] < v) { lst[y + 1] = lst[y]; y--; }
        lst[y + 1] = v;
      }
      int k1 = s_K1; if (k1 > n) k1 = n;
      unsigned long long kk = lst[k1 - 1];
      g_thr[b][type] = make_uint2((unsigned int)(kk >> 32),
                                  0xFFFFFFFFu - (unsigned int)(kk & 0xFFFFFFFFull));
    }
    __syncthreads();
  }
  if (t == 0) g_uw[b] = __fdiv_rn(1.0f, (float)(s_kept[0] + s_kept[1]));
}

__global__ void k_out(const float* __restrict__ gt_boxes, float* __restrict__ out) {
  const int TBASE = NB * NN;
  const int IBASE = TBASE + NB * NN * 4;
  const int OBASE = IBASE + NB * NN * 4;
  int bid = blockIdx.x;
  int hblk = bid % (HH / 4);
  int tmp = bid / (HH / 4);
  int a = tmp % NA;
  int b = tmp / NA;
  int w = threadIdx.x & 63;
  int h = hblk * 4 + (threadIdx.x >> 6);
  int i = (h * WW + w) * NA + a;

  int base_l = b * NN + (a * HH + h) * WW + w;
  int off = b * (NN * 4) + h * WW + w;

  unsigned char code = g_lab[b][i];
  if (code == 3) {
    out[base_l] = 0.f;
    #pragma unroll
    for (int c = 0; c < 4; c++) {
      int o = off + (a * 4 + c) * (HH * WW);
      out[TBASE + o] = 0.f; out[IBASE + o] = 0.f; out[OBASE + o] = 0.f;
    }
    return;
  }
  float lblv; bool is_pos = false, counted = false;
  if (code == 0) lblv = -1.f;
  else {
    int type = (code == 2) ? 0 : 1;
    uint2 thr = g_thr[b][type];
    unsigned int r = g_r[b][i];
    bool keep = (r > thr.x) || ((r == thr.x) && ((unsigned int)i <= thr.y));
    if (code == 2) { lblv = keep ? 1.f : -1.f; is_pos = keep; counted = keep; }
    else           { lblv = keep ? 0.f : -1.f; counted = keep; }
  }
  out[base_l] = lblv;

  int arg = g_arg[b][i];
  const float* g = gt_boxes + (b * KG + arg) * 5;
  float g0 = g[0], g1 = g[1], g2 = g[2], g3 = g[3];
  float sx = (float)(w * 16), sy = (float)(h * 16);
  float ax1 = c_base[a][0] + sx, ay1 = c_base[a][1] + sy;
  float ax2 = c_base[a][2] + sx, ay2 = c_base[a][3] + sy;
  float aw = ax2 - ax1 + 1.f, ah = ay2 - ay1 + 1.f;
  float acx = ax1 + 0.5f * (aw - 1.f), acy = ay1 + 0.5f * (ah - 1.f);
  float gw = g2 - g0 + 1.f, gh = g3 - g1 + 1.f;
  float gcx = g0 + 0.5f * (gw - 1.f), gcy = g1 + 0.5f * (gh - 1.f);
  float tx = (gcx - acx) / aw, ty = (gcy - acy) / ah;
  float tw = logf(gw / aw), th = logf(gh / ah);

  float inw = is_pos ? 1.f : 0.f;
  float ow  = counted ? g_uw[b] : 0.f;
  float tgt[4] = {tx, ty, tw, th};
  #pragma unroll
  for (int c = 0; c < 4; c++) {
    int o = off + (a * 4 + c) * (HH * WW);
    out[TBASE + o] = tgt[c];
    out[IBASE + o] = inw;
    out[OBASE + o] = ow;
  }
}

extern "C" void kernel_launch(void* const* d_in, const int* in_sizes, int n_in,
                              void* d_out, int out_size) {
  const float* gt = (const float*)d_in[1];
  const float* iminfo = (const float*)d_in[2];
  float* out = (float*)d_out;

  Keys keys;
  // partitionable: key_b = tf(key,(0,b)); kf = tf(key_b,(0,0)); kb = tf(key_b,(0,1))
  for (int b = 0; b < NB; b++) {
    unsigned int a0, a1;
    tf2x32(0u, 42u, 0u, (unsigned int)b, a0, a1);
    tf2x32(a0, a1, 0u, 0u, keys.kf[b][0], keys.kf[b][1]);
    tf2x32(a0, a1, 0u, 1u, keys.kb[b][0], keys.kb[b][1]);
  }

  k_init<<<256, 256>>>();
  dim3 g1(HW / 256, NA, NB);
  k_gtmax<<<g1, 256>>>(gt, iminfo);
  k_label<<<g1, 256>>>(gt, iminfo, keys);
  k_select<<<NB, 256>>>();
  k_out<<<NB * NA * (HH / 4), 256>>>(gt, out);
}

// round 3
// speedup vs baseline: 4.4387x; 1.6055x over previous
#include <cuda_runtime.h>
#include <cstdint>

#define NB 16
#define KG 50
#define HH 64
#define WW 64
#define NA 9
#define NN (HH*WW*NA)      // 36864
#define HW (HH*WW)         // 4096
#define SEL_CAP 2048

// base anchors (ratios 0.5/1/2 x scales 8/16/32), exact fp32 values
__constant__ float c_base[NA][4] = {
  { -84.f,  -40.f,  99.f,  55.f},
  {-176.f,  -88.f, 191.f, 103.f},
  {-360.f, -184.f, 375.f, 199.f},
  { -56.f,  -56.f,  71.f,  71.f},
  {-120.f, -120.f, 135.f, 135.f},
  {-248.f, -248.f, 263.f, 263.f},
  { -36.f,  -80.f,  51.f,  95.f},
  { -80.f, -168.f,  95.f, 183.f},
  {-168.f, -344.f, 183.f, 359.f}
};

__device__ float              g_gtmax[NB][KG];
__device__ unsigned char      g_lab[NB][NN];   // 0:-1  1:bg  2:fg  3:outside
__device__ unsigned short     g_arg[NB][NN];
__device__ unsigned int       g_r[NB][NN];     // 23-bit random mantissa (candidates only)
__device__ int                g_cnt[NB][2];
__device__ unsigned long long g_cand[NB][2][NN];  // (r<<32)|i
__device__ uint2              g_thr[NB][2];    // keep iff r>thr.x || (r==thr.x && i<=thr.y)
__device__ float              g_uw[NB];

struct Keys { unsigned int kf[NB][2]; unsigned int kb[NB][2]; };

__host__ __device__ __forceinline__ unsigned int rotl32(unsigned int x, int r) {
  return (x << r) | (x >> (32 - r));
}

__host__ __device__ __forceinline__ void tf2x32(unsigned int k0, unsigned int k1,
                                                unsigned int x0, unsigned int x1,
                                                unsigned int &o0, unsigned int &o1) {
  unsigned int ks2 = k0 ^ k1 ^ 0x1BD11BDAu;
  x0 += k0; x1 += k1;
  const int ra[4] = {13, 15, 26, 6};
  const int rb[4] = {17, 29, 16, 24};
  #pragma unroll
  for (int j = 0; j < 4; j++) { x0 += x1; x1 = rotl32(x1, ra[j]); x1 ^= x0; }
  x0 += k1;  x1 += ks2 + 1u;
  #pragma unroll
  for (int j = 0; j < 4; j++) { x0 += x1; x1 = rotl32(x1, rb[j]); x1 ^= x0; }
  x0 += ks2; x1 += k0 + 2u;
  #pragma unroll
  for (int j = 0; j < 4; j++) { x0 += x1; x1 = rotl32(x1, ra[j]); x1 ^= x0; }
  x0 += k0;  x1 += k1 + 3u;
  #pragma unroll
  for (int j = 0; j < 4; j++) { x0 += x1; x1 = rotl32(x1, rb[j]); x1 ^= x0; }
  x0 += k1;  x1 += ks2 + 4u;
  #pragma unroll
  for (int j = 0; j < 4; j++) { x0 += x1; x1 = rotl32(x1, ra[j]); x1 ^= x0; }
  x0 += ks2; x1 += k0 + 5u;
  o0 = x0; o1 = x1;
}

__device__ __forceinline__ void load_gts(const float* __restrict__ gt_boxes, int b, int t,
                                         float (*s_g)[4], float* s_ga) {
  if (t < KG) {
    const float* g = gt_boxes + (b * KG + t) * 5;
    float g0 = g[0], g1 = g[1], g2 = g[2], g3 = g[3];
    s_g[t][0] = g0; s_g[t][1] = g1; s_g[t][2] = g2; s_g[t][3] = g3;
    s_ga[t] = __fmul_rn(__fadd_rn(__fsub_rn(g2, g0), 1.0f),
                        __fadd_rn(__fsub_rn(g3, g1), 1.0f));
  }
}

__global__ void k_init() {
  int idx = threadIdx.x;
  if (idx < NB * KG) ((float*)g_gtmax)[idx] = 0.0f;
  if (idx < NB * 2)  ((int*)g_cnt)[idx] = 0;
}

// grid (HW/256, NA, NB): warp = one anchor shape, contiguous hw
__global__ void k_gtmax(const float* __restrict__ gt_boxes, const float* __restrict__ im_info) {
  __shared__ float s_g[KG][4];
  __shared__ float s_ga[KG];
  int b = blockIdx.z;
  int a = blockIdx.y;
  int t = threadIdx.x;
  load_gts(gt_boxes, b, t, s_g, s_ga);
  __syncthreads();
  int hw = blockIdx.x * blockDim.x + t;
  float img_h = im_info[0], img_w = im_info[1];
  int w = hw & 63; int h = hw >> 6;
  float sx = (float)(w * 16), sy = (float)(h * 16);
  float ax1 = c_base[a][0] + sx, ay1 = c_base[a][1] + sy;
  float ax2 = c_base[a][2] + sx, ay2 = c_base[a][3] + sy;
  bool inside = (ax1 >= 0.f) && (ay1 >= 0.f) && (ax2 < img_w) && (ay2 < img_h);
  if (!inside) return;
  float aw = __fadd_rn(__fsub_rn(ax2, ax1), 1.0f);
  float ah = __fadd_rn(__fsub_rn(ay2, ay1), 1.0f);
  float aarea = __fmul_rn(aw, ah);
  unsigned mask = __activemask();
  int lane = t & 31;
  int leader = __ffs(mask) - 1;
  #pragma unroll 5
  for (int k = 0; k < KG; k++) {
    float ix = __fadd_rn(__fsub_rn(fminf(ax2, s_g[k][2]), fmaxf(ax1, s_g[k][0])), 1.0f);
    float iy = __fadd_rn(__fsub_rn(fminf(ay2, s_g[k][3]), fmaxf(ay1, s_g[k][1])), 1.0f);
    int ovb = 0;
    if (ix > 0.f && iy > 0.f) {
      float inter = __fmul_rn(ix, iy);
      float denom = __fsub_rn(__fadd_rn(aarea, s_ga[k]), inter);
      ovb = __float_as_int(__fdiv_rn(inter, denom));
    }
    int mv = __reduce_max_sync(mask, ovb);
    if (lane == leader && mv > 0) atomicMax((int*)&g_gtmax[b][k], mv);
  }
}

__global__ void k_label(const float* __restrict__ gt_boxes, const float* __restrict__ im_info,
                        Keys keys) {
  __shared__ float s_g[KG][4];
  __shared__ float s_ga[KG];
  __shared__ float s_gm[KG];
  int b = blockIdx.z;
  int a = blockIdx.y;
  int t = threadIdx.x;
  load_gts(gt_boxes, b, t, s_g, s_ga);
  if (t < KG) {
    float gm = g_gtmax[b][t];
    s_gm[t] = (gm == 0.f) ? 1e-5f : gm;
  }
  __syncthreads();
  int hw = blockIdx.x * blockDim.x + t;
  int i = hw * NA + a;
  float img_h = im_info[0], img_w = im_info[1];
  int w = hw & 63; int h = hw >> 6;
  float sx = (float)(w * 16), sy = (float)(h * 16);
  float ax1 = c_base[a][0] + sx, ay1 = c_base[a][1] + sy;
  float ax2 = c_base[a][2] + sx, ay2 = c_base[a][3] + sy;
  bool inside = (ax1 >= 0.f) && (ay1 >= 0.f) && (ax2 < img_w) && (ay2 < img_h);

  int type = -1;            // -1: not a candidate
  unsigned char code = 3;
  if (inside) {
    float aw = __fadd_rn(__fsub_rn(ax2, ax1), 1.0f);
    float ah = __fadd_rn(__fsub_rn(ay2, ay1), 1.0f);
    float aarea = __fmul_rn(aw, ah);
    float maxov = 0.0f; int arg = 0; bool best = false;
    #pragma unroll 5
    for (int k = 0; k < KG; k++) {
      float ix = __fadd_rn(__fsub_rn(fminf(ax2, s_g[k][2]), fmaxf(ax1, s_g[k][0])), 1.0f);
      float iy = __fadd_rn(__fsub_rn(fminf(ay2, s_g[k][3]), fmaxf(ay1, s_g[k][1])), 1.0f);
      if (ix > 0.f && iy > 0.f) {
        float inter = __fmul_rn(ix, iy);
        float denom = __fsub_rn(__fadd_rn(aarea, s_ga[k]), inter);
        float ov = __fdiv_rn(inter, denom);
        if (ov > maxov) { maxov = ov; arg = k; }
        if (ov == s_gm[k]) best = true;
      }
    }
    if (best || (maxov >= 0.7f)) code = 2;
    else if (maxov < 0.3f)       code = 1;
    else                         code = 0;
    g_arg[b][i] = (unsigned short)arg;
    if (code >= 1) type = (code == 2) ? 0 : 1;
  }
  g_lab[b][i] = code;

  unsigned int r = 0;
  if (type >= 0) {
    unsigned int k0 = (type == 0) ? keys.kf[b][0] : keys.kb[b][0];
    unsigned int k1 = (type == 0) ? keys.kf[b][1] : keys.kb[b][1];
    unsigned int o0, o1;
    tf2x32(k0, k1, 0u, (unsigned int)i, o0, o1);
    r = (o0 ^ o1) >> 9;         // 23-bit mantissa; uniform strictly monotonic in r
    g_r[b][i] = r;
  }
  // warp-aggregated candidate append (full 256-thread blocks, no early exits)
  unsigned mf = __ballot_sync(0xFFFFFFFFu, type == 0);
  unsigned mb = __ballot_sync(0xFFFFFFFFu, type == 1);
  int lane = t & 31;
  unsigned lt = (1u << lane) - 1u;
  unsigned long long pk = ((unsigned long long)r << 32) | (unsigned long long)(unsigned)i;
  if (type == 0) {
    int ldr = __ffs(mf) - 1;
    int pos;
    if (lane == ldr) pos = atomicAdd(&g_cnt[b][0], __popc(mf));
    pos = __shfl_sync(mf, pos, ldr);
    g_cand[b][0][pos + __popc(mf & lt)] = pk;
  } else if (type == 1) {
    int ldr = __ffs(mb) - 1;
    int pos;
    if (lane == ldr) pos = atomicAdd(&g_cnt[b][1], __popc(mb));
    pos = __shfl_sync(mb, pos, ldr);
    g_cand[b][1][pos + __popc(mb & lt)] = pk;
  }
}

// One block per (batch,type). Scans only the compact candidate list.
__global__ void k_select() {
  __shared__ unsigned int sh[2048];
  __shared__ unsigned int ss[257];
  __shared__ unsigned long long lst[SEL_CAP];
  __shared__ int s_tb, s_K1, s_lc;

  int b = blockIdx.x >> 1;
  int type = blockIdx.x & 1;
  int t = threadIdx.x;

  int cnt = g_cnt[b][type];
  int cnt_fg = g_cnt[b][0];
  int kept_fg = min(cnt_fg, 128);
  int K = (type == 0) ? 128 : (256 - kept_fg);
  if (type == 1 && t == 0) {
    int kept_bg = min(cnt, K);
    g_uw[b] = __fdiv_rn(1.0f, (float)(kept_fg + kept_bg));
  }
  if (cnt <= K) {
    if (t == 0) g_thr[b][type] = make_uint2(0u, 0xFFFFFFFFu);  // keep all
    return;
  }
  const unsigned long long* cand = g_cand[b][type];
  for (int j = t; j < 2048; j += 256) sh[j] = 0u;
  if (t == 0) { ss[256] = 0u; s_lc = 0; }
  __syncthreads();
  for (int c = t; c < cnt; c += 256) {
    unsigned int r = (unsigned int)(cand[c] >> 32);
    atomicAdd(&sh[r >> 12], 1u);
  }
  __syncthreads();
  unsigned int cs = 0;
  #pragma unroll
  for (int k = 0; k < 8; k++) cs += sh[t * 8 + k];
  ss[t] = cs;
  __syncthreads();
  #pragma unroll
  for (int off = 1; off < 256; off <<= 1) {
    unsigned int v = (t + off < 256) ? ss[t + off] : 0u;
    __syncthreads();
    ss[t] += v;
    __syncthreads();
  }
  {
    int run = (int)ss[t + 1];
    #pragma unroll
    for (int k = 7; k >= 0; k--) {
      int j = t * 8 + k;
      int hj = (int)sh[j];
      if (run < K && run + hj >= K) { s_tb = j; s_K1 = K - run; }
      run += hj;
    }
  }
  __syncthreads();
  int tb = s_tb;
  for (int c = t; c < cnt; c += 256) {
    unsigned long long v = cand[c];
    unsigned int r = (unsigned int)(v >> 32);
    if ((int)(r >> 12) == tb) {
      int p = atomicAdd(&s_lc, 1);
      if (p < SEL_CAP)
        lst[p] = ((unsigned long long)r << 32) |
                 (unsigned long long)(0xFFFFFFFFu - (unsigned int)(v & 0xFFFFFFFFull));
    }
  }
  __syncthreads();
  if (t == 0) {
    int n = min(s_lc, SEL_CAP);
    for (int x = 1; x < n; x++) {     // descending insertion sort (n is tiny)
      unsigned long long v = lst[x]; int y = x - 1;
      while (y >= 0 && lst[y] < v) { lst[y + 1] = lst[y]; y--; }
      lst[y + 1] = v;
    }
    int k1 = s_K1; if (k1 > n) k1 = n;
    unsigned long long kk = lst[k1 - 1];
    g_thr[b][type] = make_uint2((unsigned int)(kk >> 32),
                                0xFFFFFFFFu - (unsigned int)(kk & 0xFFFFFFFFull));
  }
}

__global__ void k_out(const float* __restrict__ gt_boxes, float* __restrict__ out) {
  const int TBASE = NB * NN;
  const int IBASE = TBASE + NB * NN * 4;
  const int OBASE = IBASE + NB * NN * 4;
  int bid = blockIdx.x;
  int hblk = bid % (HH / 4);
  int tmp = bid / (HH / 4);
  int a = tmp % NA;
  int b = tmp / NA;
  int w = threadIdx.x & 63;
  int h = hblk * 4 + (threadIdx.x >> 6);
  int i = (h * WW + w) * NA + a;

  int base_l = b * NN + (a * HH + h) * WW + w;
  int off = b * (NN * 4) + h * WW + w;

  unsigned char code = g_lab[b][i];
  if (code == 3) {
    out[base_l] = 0.f;
    #pragma unroll
    for (int c = 0; c < 4; c++) {
      int o = off + (a * 4 + c) * (HH * WW);
      out[TBASE + o] = 0.f; out[IBASE + o] = 0.f; out[OBASE + o] = 0.f;
    }
    return;
  }
  float lblv; bool is_pos = false, counted = false;
  if (code == 0) lblv = -1.f;
  else {
    int type = (code == 2) ? 0 : 1;
    uint2 thr = g_thr[b][type];
    unsigned int r = g_r[b][i];
    bool keep = (r > thr.x) || ((r == thr.x) && ((unsigned int)i <= thr.y));
    if (code == 2) { lblv = keep ? 1.f : -1.f; is_pos = keep; counted = keep; }
    else           { lblv = keep ? 0.f : -1.f; counted = keep; }
  }
  out[base_l] = lblv;

  int arg = g_arg[b][i];
  const float* g = gt_boxes + (b * KG + arg) * 5;
  float g0 = g[0], g1 = g[1], g2 = g[2], g3 = g[3];
  float sx = (float)(w * 16), sy = (float)(h * 16);
  float ax1 = c_base[a][0] + sx, ay1 = c_base[a][1] + sy;
  float ax2 = c_base[a][2] + sx, ay2 = c_base[a][3] + sy;
  float aw = ax2 - ax1 + 1.f, ah = ay2 - ay1 + 1.f;
  float acx = ax1 + 0.5f * (aw - 1.f), acy = ay1 + 0.5f * (ah - 1.f);
  float gw = g2 - g0 + 1.f, gh = g3 - g1 + 1.f;
  float gcx = g0 + 0.5f * (gw - 1.f), gcy = g1 + 0.5f * (gh - 1.f);
  float tx = (gcx - acx) / aw, ty = (gcy - acy) / ah;
  float tw = logf(gw / aw), th = logf(gh / ah);

  float inw = is_pos ? 1.f : 0.f;
  float ow  = counted ? g_uw[b] : 0.f;
  float tgt[4] = {tx, ty, tw, th};
  #pragma unroll
  for (int c = 0; c < 4; c++) {
    int o = off + (a * 4 + c) * (HH * WW);
    out[TBASE + o] = tgt[c];
    out[IBASE + o] = inw;
    out[OBASE + o] = ow;
  }
}

extern "C" void kernel_launch(void* const* d_in, const int* in_sizes, int n_in,
                              void* d_out, int out_size) {
  const float* gt = (const float*)d_in[1];
  const float* iminfo = (const float*)d_in[2];
  float* out = (float*)d_out;

  Keys keys;
  // partitionable: key_b = tf(key,(0,b)); kf = tf(key_b,(0,0)); kb = tf(key_b,(0,1))
  for (int b = 0; b < NB; b++) {
    unsigned int a0, a1;
    tf2x32(0u, 42u, 0u, (unsigned int)b, a0, a1);
    tf2x32(a0, a1, 0u, 0u, keys.kf[b][0], keys.kf[b][1]);
    tf2x32(a0, a1, 0u, 1u, keys.kb[b][0], keys.kb[b][1]);
  }

  k_init<<<1, 1024>>>();
  dim3 g1(HW / 256, NA, NB);
  k_gtmax<<<g1, 256>>>(gt, iminfo);
  k_label<<<g1, 256>>>(gt, iminfo, keys);
  k_select<<<NB * 2, 256>>>();
  k_out<<<NB * NA * (HH / 4), 256>>>(gt, out);
}